// round 13
// baseline (speedup 1.0000x reference)
#include <cuda_runtime.h>
#include <cuda_fp16.h>
#include <cstdint>

#define B_   2
#define T_   2048
#define DM_  1024
#define H_   16
#define DH_  64
#define BT_  (B_ * T_)   // 4096

// Scratch (allocation-free rule: device globals) — all single fp16
__device__ __half g_x[BT_ * DM_];
__device__ __half g_w[4 * DM_ * DM_];                 // W fp16, [K,N], 4 slabs
__device__ __half g_q[BT_ * DM_];
__device__ __half g_k[BT_ * DM_];
__device__ __half g_v[BT_ * DM_];
__device__ __half g_z[BT_ * DM_];

// ===========================================================================
// Warp-MMA + cp.async helpers
// ===========================================================================
__device__ __forceinline__ uint32_t smem_u32(const void* p) {
    uint32_t a;
    asm("{ .reg .u64 t; cvta.to.shared.u64 t, %1; cvt.u32.u64 %0, t; }"
        : "=r"(a) : "l"(p));
    return a;
}

__device__ __forceinline__ void ldsm4(uint32_t* r, uint32_t addr) {
    asm volatile("ldmatrix.sync.aligned.m8n8.x4.shared.b16 {%0,%1,%2,%3}, [%4];"
                 : "=r"(r[0]), "=r"(r[1]), "=r"(r[2]), "=r"(r[3]) : "r"(addr));
}
__device__ __forceinline__ void ldsm4t(uint32_t* r, uint32_t addr) {
    asm volatile("ldmatrix.sync.aligned.m8n8.x4.trans.shared.b16 {%0,%1,%2,%3}, [%4];"
                 : "=r"(r[0]), "=r"(r[1]), "=r"(r[2]), "=r"(r[3]) : "r"(addr));
}

__device__ __forceinline__ void mma16816h(float* c, const uint32_t* a,
                                          const uint32_t* b) {
    asm volatile(
        "mma.sync.aligned.m16n8k16.row.col.f32.f16.f16.f32 "
        "{%0,%1,%2,%3}, {%4,%5,%6,%7}, {%8,%9}, {%0,%1,%2,%3};"
        : "+f"(c[0]), "+f"(c[1]), "+f"(c[2]), "+f"(c[3])
        : "r"(a[0]), "r"(a[1]), "r"(a[2]), "r"(a[3]), "r"(b[0]), "r"(b[1]));
}

#define CP_ASYNC16(dst, src) \
    asm volatile("cp.async.cg.shared.global [%0], [%1], 16;" :: "r"(dst), "l"(src))
#define CP_COMMIT() asm volatile("cp.async.commit_group;")
#define CP_WAIT1()  asm volatile("cp.async.wait_group 1;")
#define CP_WAIT0()  asm volatile("cp.async.wait_group 0;")

__device__ __forceinline__ float ex2f(float x) {
    float y;
    asm("ex2.approx.f32 %0, %1;" : "=f"(y) : "f"(x));
    return y;
}

__device__ __forceinline__ uint32_t pack_h2(float x, float y) {
    __half2 h = __floats2half2_rn(x, y);
    return *(uint32_t*)&h;
}

// ===========================================================================
// Fused conversion kernel (x + 4 weight slabs), fp32 -> fp16
// ===========================================================================
__global__ void conv_all(const float* __restrict__ x,
                         const float* __restrict__ W0, const float* __restrict__ W1,
                         const float* __restrict__ W2, const float* __restrict__ W3,
                         __half* __restrict__ xo, __half* __restrict__ wo)
{
    int y = blockIdx.y;
    if (y < 4) {
        const float* src = (y == 0) ? W0 : (y == 1) ? W1 : (y == 2) ? W2 : W3;
        size_t i = (size_t)(blockIdx.x * 256 + threadIdx.x) * 4;
        float4 v = *(const float4*)(src + i);
        *(uint2*)(wo + (size_t)y * DM_ * DM_ + i) =
            make_uint2(pack_h2(v.x, v.y), pack_h2(v.z, v.w));
    } else {
        size_t i = ((size_t)(y - 4) * 1024 + blockIdx.x) * 1024 +
                   (size_t)threadIdx.x * 4;
        float4 v = *(const float4*)(x + i);
        *(uint2*)(xo + i) = make_uint2(pack_h2(v.x, v.y), pack_h2(v.z, v.w));
    }
}

// ===========================================================================
// fp16 single-pass GEMM: 128x128 tile, BK=32, cp.async 3-stage ring,
// one __syncthreads per k-iteration. 2 CTA/SM. (unchanged from R12)
// ===========================================================================
#define GP      80
#define TSZA    (128 * GP)            // 10240
#define PITB    272
#define TSZB    (32 * PITB)           // 8704
#define STG     (TSZA + TSZB)         // 18944 per stage
#define G_SMEM  (3 * STG)             // 56832

#define QSCALE  0.1803368801111204f   // 0.125 * log2(e)

template<int MODE>
__global__ __launch_bounds__(256, 2) void gemm128(
    const __half* __restrict__ Ap, const __half* __restrict__ Wp,
    const float* __restrict__ cs, const float* __restrict__ sn,
    float* __restrict__ Cf,
    __half* __restrict__ qq, __half* __restrict__ kq, __half* __restrict__ vq)
{
    extern __shared__ __align__(16) char sm[];
    const int tid  = threadIdx.x;
    const int wid  = tid >> 5;
    const int lane = tid & 31;
    const int wm   = wid & 3;
    const int wn   = wid >> 2;
    const int widx = (MODE == 0) ? (blockIdx.x >> 3) : 3;
    const int n0   = (blockIdx.x & 7) * 128;
    const int m0   = blockIdx.y * 128;
    const uint32_t sb = smem_u32(sm);

    const __half* gA = Ap + (size_t)m0 * DM_;
    const __half* gW = Wp + (size_t)widx * DM_ * DM_ + n0;

    const int arow = tid >> 2;
    const int acg  = tid & 3;
    const int brow = tid >> 4;
    const int bcg  = tid & 15;

    #define ISSUE(st_, k0_)                                                    \
        {                                                                      \
            uint32_t dA = sb + (st_) * STG + arow * GP + acg * 16;             \
            const __half* ga = gA + (size_t)arow * DM_ + (k0_) + acg * 8;      \
            CP_ASYNC16(dA,           ga);                                      \
            CP_ASYNC16(dA + 64 * GP, ga + (size_t)64 * DM_);                   \
            uint32_t dB = sb + (st_) * STG + TSZA + brow * PITB + bcg * 16;    \
            const __half* gb = gW + (size_t)((k0_) + brow) * DM_ + bcg * 8;    \
            CP_ASYNC16(dB,             gb);                                    \
            CP_ASYNC16(dB + 16 * PITB, gb + (size_t)16 * DM_);                 \
            CP_COMMIT();                                                       \
        }

    const uint32_t a_off = (uint32_t)((lane & 15) * GP + (lane >> 4) * 16);
    const uint32_t b_off = (uint32_t)((lane & 7) * PITB +
                                      ((lane >> 3) & 1) * 8 * PITB + (lane >> 4) * 16);

    float acc[2][8][4];
    #pragma unroll
    for (int i = 0; i < 2; i++)
        #pragma unroll
        for (int j = 0; j < 8; j++)
            #pragma unroll
            for (int l = 0; l < 4; l++) acc[i][j][l] = 0.f;

    ISSUE(0, 0);
    ISSUE(1, 32);

    const int NIT = DM_ / 32;   // 32
    for (int c = 0; c < NIT; c++) {
        if (c + 1 < NIT) { CP_WAIT1(); } else { CP_WAIT0(); }
        __syncthreads();
        if (c + 2 < NIT) { ISSUE((c + 2) % 3, (c + 2) * 32); }

        const uint32_t stb = sb + (c % 3) * STG;
        #pragma unroll
        for (int ks = 0; ks < 2; ks++) {
            uint32_t af[2][4];
            #pragma unroll
            for (int mt = 0; mt < 2; mt++)
                ldsm4(af[mt], stb + (uint32_t)((wm * 32 + mt * 16) * GP + ks * 32) + a_off);
            #pragma unroll
            for (int nt = 0; nt < 4; nt++) {
                uint32_t bb = stb + TSZA + (uint32_t)(ks * 16 * PITB +
                              wn * 128 + nt * 32) + b_off;
                uint32_t th[4];
                ldsm4t(th, bb);
                #pragma unroll
                for (int mt = 0; mt < 2; mt++) {
                    mma16816h(acc[mt][2*nt],   af[mt], th);
                    mma16816h(acc[mt][2*nt+1], af[mt], th + 2);
                }
            }
        }
    }

    if (MODE == 1) {
        #pragma unroll
        for (int mt = 0; mt < 2; mt++) {
            int m = m0 + wm * 32 + mt * 16 + (lane >> 2);
            #pragma unroll
            for (int nt = 0; nt < 8; nt++) {
                int n = n0 + wn * 64 + nt * 8 + (lane & 3) * 2;
                *(float2*)(Cf + (size_t)m * DM_ + n) =
                    make_float2(acc[mt][nt][0], acc[mt][nt][1]);
                *(float2*)(Cf + (size_t)(m + 8) * DM_ + n) =
                    make_float2(acc[mt][nt][2], acc[mt][nt][3]);
            }
        }
    } else {
        __half* d = (widx == 0) ? qq : (widx == 1) ? kq : vq;
        #pragma unroll
        for (int mt = 0; mt < 2; mt++) {
            int m  = m0 + wm * 32 + mt * 16 + (lane >> 2);
            int t0 = m & (T_ - 1);
            int t1 = (m + 8) & (T_ - 1);
            #pragma unroll
            for (int nt = 0; nt < 8; nt++) {
                int n = n0 + wn * 64 + nt * 8 + (lane & 3) * 2;
                float e0 = acc[mt][nt][0], o0 = acc[mt][nt][1];
                float e1 = acc[mt][nt][2], o1 = acc[mt][nt][3];
                if (widx <= 1) {
                    int i = (n & 63) >> 1;
                    float c0 = __ldg(cs + t0 * 32 + i), s0 = __ldg(sn + t0 * 32 + i);
                    float c1 = __ldg(cs + t1 * 32 + i), s1 = __ldg(sn + t1 * 32 + i);
                    float sc = (widx == 0) ? QSCALE : 1.f;
                    float a0 = (e0 * c0 - o0 * s0) * sc, b0 = (e0 * s0 + o0 * c0) * sc;
                    float a1 = (e1 * c1 - o1 * s1) * sc, b1 = (e1 * s1 + o1 * c1) * sc;
                    e0 = a0; o0 = b0; e1 = a1; o1 = b1;
                }
                *(uint32_t*)(d + (size_t)m * DM_ + n)       = pack_h2(e0, o0);
                *(uint32_t*)(d + (size_t)(m + 8) * DM_ + n) = pack_h2(e1, o1);
            }
        }
    }
    #undef ISSUE
}

// ===========================================================================
// Tensor-core flash attention (fp16 single-pass, causal, exp2 SOFF=0).
// 4 warps x 32 q-rows per 128-row tile (128 threads, 3 CTA/SM): each K/V
// ldsm fragment now feeds 2x the MMAs (vs 8x redundant loads at 16 q-rows).
// Per-strip fused QK -> softmax -> PV; 3-stage cp.async ring.
// Balanced CTA pairs (15-bx, bx): 34 k-tiles each.
// ===========================================================================
#define PIT   144
#define V_O   9216
#define AST   18432                 // stage size (K + V tiles)
#define ATT_SMEM (3 * AST)          // 55296

__global__ __launch_bounds__(128, 3) void attn_mma(
    const __half* __restrict__ qq, const __half* __restrict__ kq,
    const __half* __restrict__ vq, __half* __restrict__ zq)
{
    extern __shared__ __align__(16) char sm[];
    const int tid  = threadIdx.x;
    const int lane = tid & 31;
    const int wq   = tid >> 5;            // 0..3, each warp owns 32 q-rows
    const int bx   = blockIdx.x;          // 0..7
    const int bh_  = blockIdx.y;
    const int b    = bh_ >> 4;
    const int h    = bh_ & 15;
    const int bT   = b * T_;
    const uint32_t sb = smem_u32(sm);
    const size_t hcol = (size_t)h * DH_;

    const uint32_t k_off = ((lane >> 4) * 8 + (lane & 7)) * PIT + ((lane >> 3) & 1) * 16;
    const uint32_t v_off = (lane & 7) * PIT + ((lane >> 3) & 1) * 8 * PIT + (lane >> 4) * 16;

    // K/V tile loader: 128 threads x 8 chunks = 16 KB
    #define AISSUE(st_, k0_)                                                   \
        {                                                                      \
            int r = tid >> 3, cc = tid & 7;                                    \
            uint32_t d = sb + (st_) * AST + r * PIT + cc * 16;                 \
            size_t g = ((size_t)(bT + (k0_) + r)) * DM_ + hcol + cc * 8;       \
            CP_ASYNC16(d,                  kq + g);                            \
            CP_ASYNC16(d + 16 * PIT,       kq + g + 16 * DM_);                 \
            CP_ASYNC16(d + 32 * PIT,       kq + g + 32 * DM_);                 \
            CP_ASYNC16(d + 48 * PIT,       kq + g + 48 * DM_);                 \
            CP_ASYNC16(d + V_O,            vq + g);                            \
            CP_ASYNC16(d + V_O + 16 * PIT, vq + g + 16 * DM_);                 \
            CP_ASYNC16(d + V_O + 32 * PIT, vq + g + 32 * DM_);                 \
            CP_ASYNC16(d + V_O + 48 * PIT, vq + g + 48 * DM_);                 \
            CP_COMMIT();                                                       \
        }

    #pragma unroll 1
    for (int ph = 0; ph < 2; ph++) {
        const int qi = ph ? bx : 15 - bx;     // heavy tile first
        const int q0 = qi * 128;
        const int nkt = 2 * qi + 2;
        int qg[2];
        qg[0] = q0 + wq * 32 + (lane >> 2);       // m-tile 0 (rows +0 / +8)
        qg[1] = qg[0] + 16;                       // m-tile 1 (rows +16 / +24)

        __syncthreads();    // all warps done reading previous phase's smem

        // ---- stage Q (128 rows) through smem, extract A-fragments ----
        {
            int r = tid >> 3, c = tid & 7;
            #pragma unroll
            for (int i = 0; i < 8; i++) {
                int row = r + i * 16;
                size_t g = ((size_t)(bT + q0 + row)) * DM_ + hcol + c * 8;
                *(uint4*)(sm + row * PIT + c * 16) = *(const uint4*)(qq + g);
            }
        }
        __syncthreads();

        uint32_t qf[4][2][4];   // [ks][mt][frag]
        {
            const uint32_t a_off = (lane & 15) * PIT + (lane >> 4) * 16;
            #pragma unroll
            for (int ks = 0; ks < 4; ks++)
                #pragma unroll
                for (int mt = 0; mt < 2; mt++)
                    ldsm4(qf[ks][mt],
                          sb + (wq * 32 + mt * 16) * PIT + ks * 32 + a_off);
        }
        __syncthreads();   // Q reads done; smem reusable for K/V stages

        AISSUE(0, 0);
        if (nkt > 1) AISSUE(1, 64);

        float o[2][8][4];
        #pragma unroll
        for (int mt = 0; mt < 2; mt++)
            #pragma unroll
            for (int i = 0; i < 8; i++)
                #pragma unroll
                for (int j = 0; j < 4; j++) o[mt][i][j] = 0.f;
        float l[2][2] = {{0.f, 0.f}, {0.f, 0.f}};

        for (int kt = 0; kt < nkt; kt++) {
            const int k0 = kt * 64;
            if (kt + 1 < nkt) { CP_WAIT1(); } else { CP_WAIT0(); }
            __syncthreads();
            if (kt + 2 < nkt) { AISSUE((kt + 2) % 3, (kt + 2) * 64); }

            const uint32_t stb = sb + (kt % 3) * AST;
            const bool diag = (kt >= nkt - 2);

            #pragma unroll
            for (int nt2 = 0; nt2 < 4; nt2++) {
                // ---- QK strip: both m-tiles share each K fragment ----
                float s[2][8];
                #pragma unroll
                for (int mt = 0; mt < 2; mt++)
                    #pragma unroll
                    for (int j = 0; j < 8; j++) s[mt][j] = 0.f;

                #pragma unroll
                for (int ks = 0; ks < 4; ks++) {
                    uint32_t th[4];
                    ldsm4(th, stb + (nt2 * 16) * PIT + ks * 32 + k_off);
                    #pragma unroll
                    for (int mt = 0; mt < 2; mt++) {
                        mma16816h(s[mt],     qf[ks][mt], th);
                        mma16816h(s[mt] + 4, qf[ks][mt], th + 2);
                    }
                }

                if (diag) {
                    int kg = k0 + nt2 * 16 + (lane & 3) * 2;
                    #pragma unroll
                    for (int mt = 0; mt < 2; mt++) {
                        int qlo = qg[mt], qhi = qg[mt] + 8;
                        if (kg     > qlo) s[mt][0] = -1e30f;
                        if (kg + 1 > qlo) s[mt][1] = -1e30f;
                        if (kg     > qhi) s[mt][2] = -1e30f;
                        if (kg + 1 > qhi) s[mt][3] = -1e30f;
                        if (kg + 8 > qlo) s[mt][4] = -1e30f;
                        if (kg + 9 > qlo) s[mt][5] = -1e30f;
                        if (kg + 8 > qhi) s[mt][6] = -1e30f;
                        if (kg + 9 > qhi) s[mt][7] = -1e30f;
                    }
                }

                // ---- softmax strip ----
                uint32_t pf[2][4];
                #pragma unroll
                for (int mt = 0; mt < 2; mt++) {
                    #pragma unroll
                    for (int j = 0; j < 8; j++) s[mt][j] = ex2f(s[mt][j]);
                    l[mt][0] += s[mt][0] + s[mt][1] + s[mt][4] + s[mt][5];
                    l[mt][1] += s[mt][2] + s[mt][3] + s[mt][6] + s[mt][7];
                    pf[mt][0] = pack_h2(s[mt][0], s[mt][1]);
                    pf[mt][1] = pack_h2(s[mt][2], s[mt][3]);
                    pf[mt][2] = pack_h2(s[mt][4], s[mt][5]);
                    pf[mt][3] = pack_h2(s[mt][6], s[mt][7]);
                }

                // ---- PV strip: both m-tiles share each V fragment ----
                #pragma unroll
                for (int d2 = 0; d2 < 4; d2++) {
                    uint32_t tv[4];
                    ldsm4t(tv, stb + V_O + (nt2 * 16) * PIT + d2 * 32 + v_off);
                    #pragma unroll
                    for (int mt = 0; mt < 2; mt++) {
                        mma16816h(o[mt][2*d2],   pf[mt], tv);
                        mma16816h(o[mt][2*d2+1], pf[mt], tv + 2);
                    }
                }
            }
        }

        // ---- epilogue ----
        #pragma unroll
        for (int mt = 0; mt < 2; mt++) {
            float l0 = l[mt][0], l1 = l[mt][1];
            l0 += __shfl_xor_sync(0xffffffffu, l0, 1);
            l0 += __shfl_xor_sync(0xffffffffu, l0, 2);
            l1 += __shfl_xor_sync(0xffffffffu, l1, 1);
            l1 += __shfl_xor_sync(0xffffffffu, l1, 2);
            float il0 = 1.f / l0, il1 = 1.f / l1;
            size_t out = ((size_t)(bT + qg[mt])) * DM_ + hcol + (lane & 3) * 2;
            #pragma unroll
            for (int nt = 0; nt < 8; nt++) {
                *(uint32_t*)(zq + out + nt * 8) =
                    pack_h2(o[mt][nt][0] * il0, o[mt][nt][1] * il0);
                *(uint32_t*)(zq + out + 8 * DM_ + nt * 8) =
                    pack_h2(o[mt][nt][2] * il1, o[mt][nt][3] * il1);
            }
        }
    }
    #undef AISSUE
}

// ---------------------------------------------------------------------------
extern "C" void kernel_launch(void* const* d_in, const int* in_sizes, int n_in,
                              void* d_out, int out_size)
{
    const float* x  = (const float*)d_in[0];
    const float* cs = (const float*)d_in[1];
    const float* sn = (const float*)d_in[2];
    const float* Wq = (const float*)d_in[3];
    const float* Wk = (const float*)d_in[4];
    const float* Wv = (const float*)d_in[5];
    const float* Wo = (const float*)d_in[6];
    float* out = (float*)d_out;

    __half *xp, *wp, *qp, *kp, *vp, *zp;
    cudaGetSymbolAddress((void**)&xp, g_x);
    cudaGetSymbolAddress((void**)&wp, g_w);
    cudaGetSymbolAddress((void**)&qp, g_q);
    cudaGetSymbolAddress((void**)&kp, g_k);
    cudaGetSymbolAddress((void**)&vp, g_v);
    cudaGetSymbolAddress((void**)&zp, g_z);

    cudaFuncSetAttribute(gemm128<0>, cudaFuncAttributeMaxDynamicSharedMemorySize, G_SMEM);
    cudaFuncSetAttribute(gemm128<1>, cudaFuncAttributeMaxDynamicSharedMemorySize, G_SMEM);
    cudaFuncSetAttribute(attn_mma, cudaFuncAttributeMaxDynamicSharedMemorySize, ATT_SMEM);

    // fp32 -> fp16 conversions (one launch)
    conv_all<<<dim3(1024, 8), 256>>>(x, Wq, Wk, Wv, Wo, xp, wp);

    // fused QKV GEMM + RoPE epilogue
    gemm128<0><<<dim3(24, BT_ / 128), 256, G_SMEM>>>(
        xp, wp, cs, sn, nullptr, qp, kp, vp);

    attn_mma<<<dim3(8, B_ * H_), 128, ATT_SMEM>>>(qp, kp, vp, zp);

    // out = z Wo
    gemm128<1><<<dim3(8, BT_ / 128), 256, G_SMEM>>>(
        zp, wp, cs, sn, out, nullptr, nullptr, nullptr);
}